// round 8
// baseline (speedup 1.0000x reference)
#include <cuda_runtime.h>
#include <cstdint>

// Problem constants: B=2, C=256, T=512, F=128, N=4 heads, H=CN=64, D=H*F=8192
#define TFsz 65536            // T*F
typedef unsigned long long u64;

// -------- scratch (device globals; no allocations allowed) --------
__device__ float g_Y3[100663296];   // [3][B][256][TF] Q,K,V (pre-norm)
__device__ float g_Sp[8388608];     // [4 kchunks][8 g][512][512] partial scores
__device__ float g_S[2097152];      // [8][512][512] attention probs
__device__ float g_Z[33554432];     // [B][256][TF] permuted attention output
__device__ float g_Yp[33554432];    // [B][256][TF] final conv output (pre-norm)
__device__ float2 g_part[12288];    // partial (sum, sumsq) from GEMM epilogues
__device__ float2 g_stats[32];      // (mu, rstd): [0..23] qkv groups, [24..25] final

// -------- PTX helpers (portable; no "a"-gated features) --------
__device__ __forceinline__ uint32_t smem_u32(const void* p) {
    uint32_t a;
    asm("{ .reg .u64 t; cvta.to.shared.u64 t, %1; cvt.u32.u64 %0, t; }" : "=r"(a) : "l"(p));
    return a;
}
__device__ __forceinline__ uint32_t f2tf32(float v) {
    uint32_t r; asm("cvt.rna.tf32.f32 %0, %1;" : "=r"(r) : "f"(v)); return r;
}
__device__ __forceinline__ void mma_tf32(float c[4], const uint32_t a[4], const uint32_t b[2]) {
    asm volatile(
        "mma.sync.aligned.m16n8k8.row.col.f32.tf32.tf32.f32 "
        "{%0,%1,%2,%3}, {%4,%5,%6,%7}, {%8,%9}, {%0,%1,%2,%3};"
        : "+f"(c[0]), "+f"(c[1]), "+f"(c[2]), "+f"(c[3])
        : "r"(a[0]), "r"(a[1]), "r"(a[2]), "r"(a[3]), "r"(b[0]), "r"(b[1]));
}
// ldmatrix over 32-bit data: each m8n8.b16 matrix = 8x4 tf32 quadrant; thread l
// receives element (row l>>2, col l&3) -- exactly the m16n8k8 fragment map.
#define LDSM4(r0, r1, r2, r3, addr) \
    asm volatile("ldmatrix.sync.aligned.m8n8.x4.shared.b16 {%0,%1,%2,%3}, [%4];" \
                 : "=r"(r0), "=r"(r1), "=r"(r2), "=r"(r3) : "r"(addr))
#define LDSM2(r0, r1, addr) \
    asm volatile("ldmatrix.sync.aligned.m8n8.x2.shared.b16 {%0,%1}, [%2];" \
                 : "=r"(r0), "=r"(r1) : "r"(addr))

__device__ __forceinline__ float napply(float v, float gg, float of) {
    float y = fmaf(v, gg, of);
    return (y >= 0.f) ? y : 0.25f * y;
}

// ---------------------------------------------------------------------------
// tf32 mma.sync conv GEMM: Out[tens*2+b][o][j] = bias[o] + sum_c W[o][c]*X[b][c][j]
// Block 128(o) x 128(j), K-chunks of 32; 8 warps, each 4x4 m16n8k8.
// A (W) fragments via ldmatrix.x4; B (X) via scalar LDS (layout is [k][j]).
// Epilogue fuses bias + per-64-channel-group (sum,sumsq) partials.
// ---------------------------------------------------------------------------
__global__ void __launch_bounds__(256, 2) conv_mma_kernel(
    const float* __restrict__ X, float* __restrict__ Out,
    const float* __restrict__ W0, const float* __restrict__ W1, const float* __restrict__ W2,
    const float* __restrict__ b0_, const float* __restrict__ b1_, const float* __restrict__ b2_,
    float2* __restrict__ part)
{
    __shared__ __align__(16) uint32_t Ws[128][36];   // [o][k] tf32, pitch 36
    __shared__ __align__(16) uint32_t Xs[32][136];   // [k][j] tf32, pitch 136

    const int bb = blockIdx.z;
    const int y = blockIdx.y;
    const int tens = y >> 1;
    const int o0 = (y & 1) * 128;
    const int j0 = blockIdx.x * 128;
    const float* W    = (tens == 0) ? W0 : (tens == 1) ? W1 : W2;
    const float* bias = (tens == 0) ? b0_ : (tens == 1) ? b1_ : b2_;
    const float* Xb = X + (size_t)bb * (256 * (size_t)TFsz);
    float* O = Out + ((size_t)tens * 2 + bb) * (256 * (size_t)TFsz);

    const int tid = threadIdx.x;
    const int w = tid >> 5, l = tid & 31;
    const int g = l >> 2, t = l & 3;
    const int orow = w >> 2;
    const int jcol = w & 3;

    // ldmatrix A addresses (loop-invariant): quadrant row (l&15), col half (l&16)>>2
    const uint32_t sbW = smem_u32(&Ws[0][0]);
    uint32_t a_addr[4];
#pragma unroll
    for (int mt = 0; mt < 4; mt++)
        a_addr[mt] = sbW + (((orow * 64 + mt * 16 + (l & 15)) * 36) + ((l & 16) >> 2)) * 4;

    float c[4][4][4];
#pragma unroll
    for (int mt = 0; mt < 4; mt++)
#pragma unroll
        for (int nt = 0; nt < 4; nt++)
#pragma unroll
            for (int i = 0; i < 4; i++) c[mt][nt][i] = 0.f;

    for (int kc = 0; kc < 8; kc++) {
        float4 wv[4], xv[4];
#pragma unroll
        for (int it = 0; it < 4; it++) {
            int i4 = tid + it * 256;
            int row = i4 >> 3, col4 = i4 & 7;
            wv[it] = *reinterpret_cast<const float4*>(
                &W[(size_t)(o0 + row) * 256 + kc * 32 + col4 * 4]);
            int xr = i4 >> 5, xc4 = i4 & 31;
            xv[it] = *reinterpret_cast<const float4*>(
                &Xb[(size_t)(kc * 32 + xr) * TFsz + j0 + xc4 * 4]);
        }
        __syncthreads();
#pragma unroll
        for (int it = 0; it < 4; it++) {
            int i4 = tid + it * 256;
            int row = i4 >> 3, col4 = i4 & 7;
            Ws[row][col4 * 4 + 0] = f2tf32(wv[it].x);
            Ws[row][col4 * 4 + 1] = f2tf32(wv[it].y);
            Ws[row][col4 * 4 + 2] = f2tf32(wv[it].z);
            Ws[row][col4 * 4 + 3] = f2tf32(wv[it].w);
            int xr = i4 >> 5, xc4 = i4 & 31;
            uint4 u;
            u.x = f2tf32(xv[it].x); u.y = f2tf32(xv[it].y);
            u.z = f2tf32(xv[it].z); u.w = f2tf32(xv[it].w);
            *reinterpret_cast<uint4*>(&Xs[xr][xc4 * 4]) = u;
        }
        __syncthreads();

#pragma unroll
        for (int ks = 0; ks < 4; ks++) {
            const int kk = ks * 8;
            uint32_t a[4][4], b[4][2];
#pragma unroll
            for (int mt = 0; mt < 4; mt++)
                LDSM4(a[mt][0], a[mt][1], a[mt][2], a[mt][3], a_addr[mt] + kk * 4);
#pragma unroll
            for (int nt = 0; nt < 4; nt++) {
                int jw = jcol * 32 + nt * 8 + g;
                b[nt][0] = Xs[kk + t][jw];
                b[nt][1] = Xs[kk + t + 4][jw];
            }
#pragma unroll
            for (int mt = 0; mt < 4; mt++)
#pragma unroll
                for (int nt = 0; nt < 4; nt++)
                    mma_tf32(c[mt][nt], a[mt], b[nt]);
        }
        __syncthreads();
    }

    float bl[4], bh[4];
#pragma unroll
    for (int mt = 0; mt < 4; mt++) {
        bl[mt] = __ldg(&bias[o0 + orow * 64 + mt * 16 + g]);
        bh[mt] = __ldg(&bias[o0 + orow * 64 + mt * 16 + g + 8]);
    }
    float s = 0.f, sq = 0.f;
#pragma unroll
    for (int mt = 0; mt < 4; mt++) {
        const int o_lo = o0 + orow * 64 + mt * 16 + g;
#pragma unroll
        for (int nt = 0; nt < 4; nt++) {
            const int jj = j0 + jcol * 32 + nt * 8 + 2 * t;
            float v0 = c[mt][nt][0] + bl[mt];
            float v1 = c[mt][nt][1] + bl[mt];
            float v2 = c[mt][nt][2] + bh[mt];
            float v3 = c[mt][nt][3] + bh[mt];
            *reinterpret_cast<float2*>(&O[(size_t)o_lo * TFsz + jj]) = make_float2(v0, v1);
            *reinterpret_cast<float2*>(&O[(size_t)(o_lo + 8) * TFsz + jj]) = make_float2(v2, v3);
            s  += (v0 + v1) + (v2 + v3);
            sq += (v0 * v0 + v1 * v1) + (v2 * v2 + v3 * v3);
        }
    }

    __syncthreads();
    float* redS = reinterpret_cast<float*>(&Ws[0][0]);
    float* redQ = redS + 256;
    redS[tid] = s; redQ[tid] = sq;
    __syncthreads();
    const int r = tid & 127;
    for (int off = 64; off > 0; off >>= 1) {
        if (r < off) { redS[tid] += redS[tid + off]; redQ[tid] += redQ[tid + off]; }
        __syncthreads();
    }
    if (r == 0) {
        int og = (y & 1) * 2 + (tid >> 7);
        part[(((size_t)tens * 2 + bb) * 4 + og) * 512 + blockIdx.x] =
            make_float2(redS[tid], redQ[tid]);
    }
}

// ---------------------------------------------------------------------------
// Final reduction over `count` consecutive partials per group -> (mu, rstd)
// ---------------------------------------------------------------------------
__global__ void __launch_bounds__(256) reduce_final_kernel(
    const float2* __restrict__ part, float2* __restrict__ stats, int count, float inv_n)
{
    const int g = blockIdx.x;
    float s = 0.f, s2 = 0.f;
    for (int i = threadIdx.x; i < count; i += 256) {
        float2 v = part[(size_t)g * count + i];
        s += v.x; s2 += v.y;
    }
    __shared__ float sh[256], sh2[256];
    int t = threadIdx.x;
    sh[t] = s; sh2[t] = s2;
    __syncthreads();
    for (int off = 128; off > 0; off >>= 1) {
        if (t < off) { sh[t] += sh[t + off]; sh2[t] += sh2[t + off]; }
        __syncthreads();
    }
    if (t == 0) {
        float mu = sh[0] * inv_n;
        float var = fmaxf(sh2[0] * inv_n - mu * mu, 0.f);
        stats[g] = make_float2(mu, rsqrtf(var + 1e-6f));
    }
}

// ---------------------------------------------------------------------------
// QK via tf32 mma.sync (NT, split-K x4): Sp[c][g][t][s] = scale*sum Q'(t,k)K'(s,k)
// Norm+PReLU+tf32 at smem store. A (Q) via ldmatrix.x4, B (K) via ldmatrix.x2
// (both tiles [row][k] pitch 36, conflict-free: row stride = 4 banks).
// grid (4 s-tiles, 4 t-tiles, 32 = g*4+c), 256 threads.
// ---------------------------------------------------------------------------
__global__ void __launch_bounds__(256, 2) qk_mma_kernel(
    const float* __restrict__ gq, const float* __restrict__ betaq,
    const float* __restrict__ gk, const float* __restrict__ betak)
{
    __shared__ __align__(16) uint32_t Qs[128][36];
    __shared__ __align__(16) uint32_t Ks[128][36];
    __shared__ float sgg[2][64], sof[2][64];

    const int z = blockIdx.z;
    const int g = z >> 2, c = z & 3;
    const int n = g & 3;
    const float* Q  = g_Y3 + (size_t)g * 4194304;
    const float* Km = g_Y3 + 8ull * 4194304 + (size_t)g * 4194304;
    const int t0 = blockIdx.y * 128, s0 = blockIdx.x * 128;
    const int tid = threadIdx.x;
    const int w = tid >> 5, l = tid & 31;
    const int fg = l >> 2, ft = l & 3;
    const int orow = w >> 2, jcol = w & 3;

    if (tid < 128) {
        int which = tid >> 6, h = tid & 63, o = n * 64 + h;
        float2 st = g_stats[which * 8 + g];
        const float* gw = which ? gk : gq;
        const float* bw = which ? betak : betaq;
        float gg = gw[o] * st.y;
        sgg[which][h] = gg;
        sof[which][h] = bw[o] - st.x * gg;
    }
    __syncthreads();

    const uint32_t sbQ = smem_u32(&Qs[0][0]);
    const uint32_t sbK = smem_u32(&Ks[0][0]);
    uint32_t a_addr[4], b_addr[4];
#pragma unroll
    for (int mt = 0; mt < 4; mt++)
        a_addr[mt] = sbQ + (((orow * 64 + mt * 16 + (l & 15)) * 36) + ((l & 16) >> 2)) * 4;
#pragma unroll
    for (int nt = 0; nt < 4; nt++)
        b_addr[nt] = sbK + (((jcol * 32 + nt * 8 + (l & 7)) * 36) + ((l & 8) >> 1)) * 4;

    float acc[4][4][4];
#pragma unroll
    for (int mt = 0; mt < 4; mt++)
#pragma unroll
        for (int nt = 0; nt < 4; nt++)
#pragma unroll
            for (int i = 0; i < 4; i++) acc[mt][nt][i] = 0.f;

    for (int kc = 0; kc < 64; kc++) {
        const int k0 = c * 2048 + kc * 32;
        const int h = k0 >> 7;
        const size_t hb = (size_t)h * 65536 + (size_t)(k0 & 127);
        const float ggq = sgg[0][h], ofq = sof[0][h];
        const float ggk = sgg[1][h], ofk = sof[1][h];
        float4 qv[4], kv[4];
#pragma unroll
        for (int it = 0; it < 4; it++) {
            int i4 = tid + it * 256;
            int r = i4 >> 3, c4 = i4 & 7;
            qv[it] = *reinterpret_cast<const float4*>(&Q[hb + (size_t)(t0 + r) * 128 + c4 * 4]);
            kv[it] = *reinterpret_cast<const float4*>(&Km[hb + (size_t)(s0 + r) * 128 + c4 * 4]);
        }
        __syncthreads();
#pragma unroll
        for (int it = 0; it < 4; it++) {
            int i4 = tid + it * 256;
            int r = i4 >> 3, c4 = i4 & 7;
            uint4 uq, uk;
            uq.x = f2tf32(napply(qv[it].x, ggq, ofq));
            uq.y = f2tf32(napply(qv[it].y, ggq, ofq));
            uq.z = f2tf32(napply(qv[it].z, ggq, ofq));
            uq.w = f2tf32(napply(qv[it].w, ggq, ofq));
            *reinterpret_cast<uint4*>(&Qs[r][c4 * 4]) = uq;
            uk.x = f2tf32(napply(kv[it].x, ggk, ofk));
            uk.y = f2tf32(napply(kv[it].y, ggk, ofk));
            uk.z = f2tf32(napply(kv[it].z, ggk, ofk));
            uk.w = f2tf32(napply(kv[it].w, ggk, ofk));
            *reinterpret_cast<uint4*>(&Ks[r][c4 * 4]) = uk;
        }
        __syncthreads();

#pragma unroll
        for (int ks = 0; ks < 4; ks++) {
            const int kk = ks * 8;
            uint32_t a[4][4], b[4][2];
#pragma unroll
            for (int mt = 0; mt < 4; mt++)
                LDSM4(a[mt][0], a[mt][1], a[mt][2], a[mt][3], a_addr[mt] + kk * 4);
#pragma unroll
            for (int nt = 0; nt < 4; nt++)
                LDSM2(b[nt][0], b[nt][1], b_addr[nt] + kk * 4);
#pragma unroll
            for (int mt = 0; mt < 4; mt++)
#pragma unroll
                for (int nt = 0; nt < 4; nt++)
                    mma_tf32(acc[mt][nt], a[mt], b[nt]);
        }
        __syncthreads();
    }

    const float scale = 0.011048543456039806f;   // 1/sqrt(8192)
    float* Sg = g_Sp + (size_t)c * 2097152 + (size_t)g * 262144;
#pragma unroll
    for (int mt = 0; mt < 4; mt++) {
        const int tl = t0 + orow * 64 + mt * 16 + fg;
#pragma unroll
        for (int nt = 0; nt < 4; nt++) {
            const int sl = s0 + jcol * 32 + nt * 8 + 2 * ft;
            *reinterpret_cast<float2*>(&Sg[(size_t)tl * 512 + sl]) =
                make_float2(acc[mt][nt][0] * scale, acc[mt][nt][1] * scale);
            *reinterpret_cast<float2*>(&Sg[(size_t)(tl + 8) * 512 + sl]) =
                make_float2(acc[mt][nt][2] * scale, acc[mt][nt][3] * scale);
        }
    }
}

// ---------------------------------------------------------------------------
// Row softmax over 512, fusing the split-K partial sum. 4096 blocks.
// ---------------------------------------------------------------------------
__global__ void __launch_bounds__(256) softmax_kernel()
{
    const size_t row = (size_t)blockIdx.x * 512;
    const int t = threadIdx.x;
    float a = 0.f, b = 0.f;
#pragma unroll
    for (int c = 0; c < 4; c++) {
        const float* p = g_Sp + (size_t)c * 2097152 + row;
        a += p[t]; b += p[t + 256];
    }
    __shared__ float sh[256];
    sh[t] = fmaxf(a, b);
    __syncthreads();
    for (int off = 128; off > 0; off >>= 1) {
        if (t < off) sh[t] = fmaxf(sh[t], sh[t + off]);
        __syncthreads();
    }
    float m = sh[0];
    __syncthreads();
    float e0 = __expf(a - m), e1 = __expf(b - m);
    sh[t] = e0 + e1;
    __syncthreads();
    for (int off = 128; off > 0; off >>= 1) {
        if (t < off) sh[t] += sh[t + off];
        __syncthreads();
    }
    float inv = 1.0f / sh[0];
    float* q = g_S + row;
    q[t] = e0 * inv;
    q[t + 256] = e1 * inv;
}

// ---------------------------------------------------------------------------
// PV via tf32 mma.sync, output-transposed: M=f(128), N=t(128), K=s(512).
// A (V) scalar LDS from [s][f] tile; B (P) via ldmatrix.x2 from [t][s] tile.
// C pairs are consecutive t -> float2 stores into permuted Z layout.
// grid (64 cn, 4 t-tiles, 8 groups), 256 threads.
// ---------------------------------------------------------------------------
__global__ void __launch_bounds__(256, 2) pv_mma_kernel(
    const float* __restrict__ gv, const float* __restrict__ betav)
{
    __shared__ __align__(16) uint32_t Vs[32][136];   // [s][f] tf32
    __shared__ __align__(16) uint32_t Ps[128][36];   // [t][s] tf32

    const int g = blockIdx.z;
    const int n = g & 3, bb = g >> 2;
    const float* P = g_S + (size_t)g * 262144;
    const int cn = blockIdx.x;
    const float* Vb = g_Y3 + 16ull * 4194304 + (size_t)g * 4194304 + (size_t)cn * 65536;
    const int t0 = blockIdx.y * 128;
    float* Zb = g_Z + ((size_t)bb * 256 + (size_t)(n * 64 + cn)) * 65536;

    const int tid = threadIdx.x;
    const int w = tid >> 5, l = tid & 31;
    const int fg = l >> 2, ft = l & 3;
    const int orow = w >> 2, jcol = w & 3;

    float2 stv = g_stats[16 + g];
    const float ggv = gv[n * 64 + cn] * stv.y;
    const float ofv = betav[n * 64 + cn] - stv.x * ggv;

    const uint32_t sbP = smem_u32(&Ps[0][0]);
    uint32_t b_addr[4];
#pragma unroll
    for (int nt = 0; nt < 4; nt++)
        b_addr[nt] = sbP + (((jcol * 32 + nt * 8 + (l & 7)) * 36) + ((l & 8) >> 1)) * 4;

    float acc[4][4][4];
#pragma unroll
    for (int mt = 0; mt < 4; mt++)
#pragma unroll
        for (int nt = 0; nt < 4; nt++)
#pragma unroll
            for (int i = 0; i < 4; i++) acc[mt][nt][i] = 0.f;

    for (int kc = 0; kc < 16; kc++) {
        float4 vv[4], pp[4];
#pragma unroll
        for (int it = 0; it < 4; it++) {
            int i4 = tid + it * 256;
            int vr = i4 >> 5, vc4 = i4 & 31;
            vv[it] = *reinterpret_cast<const float4*>(&Vb[(size_t)(kc * 32 + vr) * 128 + vc4 * 4]);
            int pr = i4 >> 3, pc4 = i4 & 7;
            pp[it] = *reinterpret_cast<const float4*>(&P[(size_t)(t0 + pr) * 512 + kc * 32 + pc4 * 4]);
        }
        __syncthreads();
#pragma unroll
        for (int it = 0; it < 4; it++) {
            int i4 = tid + it * 256;
            int vr = i4 >> 5, vc4 = i4 & 31;
            uint4 u;
            u.x = f2tf32(napply(vv[it].x, ggv, ofv));
            u.y = f2tf32(napply(vv[it].y, ggv, ofv));
            u.z = f2tf32(napply(vv[it].z, ggv, ofv));
            u.w = f2tf32(napply(vv[it].w, ggv, ofv));
            *reinterpret_cast<uint4*>(&Vs[vr][vc4 * 4]) = u;
            int pr = i4 >> 3, pc4 = i4 & 7;
            Ps[pr][pc4 * 4 + 0] = f2tf32(pp[it].x);
            Ps[pr][pc4 * 4 + 1] = f2tf32(pp[it].y);
            Ps[pr][pc4 * 4 + 2] = f2tf32(pp[it].z);
            Ps[pr][pc4 * 4 + 3] = f2tf32(pp[it].w);
        }
        __syncthreads();

#pragma unroll
        for (int ks = 0; ks < 4; ks++) {
            const int kk = ks * 8;
            uint32_t a[4][4], b[4][2];
#pragma unroll
            for (int mt = 0; mt < 4; mt++) {
                int fw = orow * 64 + mt * 16 + fg;
                a[mt][0] = Vs[kk + ft][fw];
                a[mt][1] = Vs[kk + ft][fw + 8];
                a[mt][2] = Vs[kk + ft + 4][fw];
                a[mt][3] = Vs[kk + ft + 4][fw + 8];
            }
#pragma unroll
            for (int nt = 0; nt < 4; nt++)
                LDSM2(b[nt][0], b[nt][1], b_addr[nt] + kk * 4);
#pragma unroll
            for (int mt = 0; mt < 4; mt++)
#pragma unroll
                for (int nt = 0; nt < 4; nt++)
                    mma_tf32(acc[mt][nt], a[mt], b[nt]);
        }
        __syncthreads();
    }

    // C: (m=f, n=t_local); c0/c1 consecutive t, c2/c3 at f+8
#pragma unroll
    for (int mt = 0; mt < 4; mt++) {
        const int f = orow * 64 + mt * 16 + fg;
#pragma unroll
        for (int nt = 0; nt < 4; nt++) {
            const int tt = t0 + jcol * 32 + nt * 8 + 2 * ft;
            *reinterpret_cast<float2*>(&Zb[(size_t)f * 512 + tt]) =
                make_float2(acc[mt][nt][0], acc[mt][nt][1]);
            *reinterpret_cast<float2*>(&Zb[(size_t)(f + 8) * 512 + tt]) =
                make_float2(acc[mt][nt][2], acc[mt][nt][3]);
        }
    }
}

// ---------------------------------------------------------------------------
// Final: out = PReLU(norm(Yp)*gp + betap) + x
// ---------------------------------------------------------------------------
__global__ void __launch_bounds__(256) apply_final_kernel(
    const float* __restrict__ x, const float* __restrict__ gp,
    const float* __restrict__ betap, const float2* __restrict__ stats2,
    float* __restrict__ out)
{
    size_t i = ((size_t)blockIdx.x * 256 + threadIdx.x) * 4;
    int r = (int)(i >> 16);
    int bidx = r >> 8;
    int o = r & 255;
    float2 st = stats2[bidx];
    float gg = gp[o] * st.y;
    float ofs = betap[o] - st.x * gg;
    float4 v  = *reinterpret_cast<const float4*>(&g_Yp[i]);
    float4 xr = *reinterpret_cast<const float4*>(&x[i]);
    v.x = fmaf(v.x, gg, ofs); v.x = ((v.x >= 0.f) ? v.x : 0.25f * v.x) + xr.x;
    v.y = fmaf(v.y, gg, ofs); v.y = ((v.y >= 0.f) ? v.y : 0.25f * v.y) + xr.y;
    v.z = fmaf(v.z, gg, ofs); v.z = ((v.z >= 0.f) ? v.z : 0.25f * v.z) + xr.z;
    v.w = fmaf(v.w, gg, ofs); v.w = ((v.w >= 0.f) ? v.w : 0.25f * v.w) + xr.w;
    *reinterpret_cast<float4*>(&out[i]) = v;
}

// ---------------------------------------------------------------------------
extern "C" void kernel_launch(void* const* d_in, const int* in_sizes, int n_in,
                              void* d_out, int out_size)
{
    const float* x     = (const float*)d_in[0];
    const float* Wq    = (const float*)d_in[1];
    const float* bq    = (const float*)d_in[2];
    const float* gq    = (const float*)d_in[3];
    const float* betaq = (const float*)d_in[4];
    const float* Wk    = (const float*)d_in[5];
    const float* bk    = (const float*)d_in[6];
    const float* gk    = (const float*)d_in[7];
    const float* betak = (const float*)d_in[8];
    const float* Wv    = (const float*)d_in[9];
    const float* bv    = (const float*)d_in[10];
    const float* gv    = (const float*)d_in[11];
    const float* betav = (const float*)d_in[12];
    const float* Wp    = (const float*)d_in[13];
    const float* bp    = (const float*)d_in[14];
    const float* gp    = (const float*)d_in[15];
    const float* betap = (const float*)d_in[16];

    float *Y3, *Z, *Yp;
    float2 *part, *stats;
    cudaGetSymbolAddress((void**)&Y3,   g_Y3);
    cudaGetSymbolAddress((void**)&Z,    g_Z);
    cudaGetSymbolAddress((void**)&Yp,   g_Yp);
    cudaGetSymbolAddress((void**)&part, g_part);
    cudaGetSymbolAddress((void**)&stats, g_stats);

    // 1) QKV projections via tf32 mma.sync (+ fused norm partials)
    conv_mma_kernel<<<dim3(512, 6, 2), 256>>>(x, Y3, Wq, Wk, Wv, bq, bk, bv, part);
    // 2) finalize QKV GroupNorm stats: 24 groups x 512 partials
    reduce_final_kernel<<<24, 256>>>(part, stats, 512, 1.0f / 4194304.0f);
    // 3) S partials = scale * Q'K'^T  (mma.sync + ldmatrix, split-K x4)
    qk_mma_kernel<<<dim3(4, 4, 32), 256>>>(gq, betaq, gk, betak);
    // 4) softmax rows (fuses split-K reduction)
    softmax_kernel<<<4096, 256>>>();
    // 5) Vo = P V' (mma.sync + ldmatrix, norm fused), permuted write into Z
    pv_mma_kernel<<<dim3(64, 4, 8), 256>>>(gv, betav);
    // 6) final projection via tf32 mma.sync (+ fused norm partials)
    conv_mma_kernel<<<dim3(512, 2, 2), 256>>>(Z, Yp, Wp, Wp, Wp, bp, bp, bp, part);
    // 7) finalize per-sample stats: 2 groups x 2048 partials
    reduce_final_kernel<<<2, 256>>>(part, stats + 24, 2048, 1.0f / 16777216.0f);
    // 8) normalize + PReLU + residual
    apply_final_kernel<<<32768, 256>>>(x, gp, betap, stats + 24, (float*)d_out);
}

// round 9
// speedup vs baseline: 1.1109x; 1.1109x over previous
#include <cuda_runtime.h>
#include <cstdint>

// Problem constants: B=2, C=256, T=512, F=128, N=4 heads, H=CN=64, D=H*F=8192
#define TFsz 65536            // T*F
typedef unsigned long long u64;

// -------- scratch (device globals; no allocations allowed) --------
__device__ float g_Y3[100663296];   // [3][B][256][TF] Q,K,V (pre-norm)
__device__ float g_Sp[8388608];     // [4 kchunks][8 g][512][512] partial scores
__device__ float g_S[2097152];      // [8][512][512] attention probs
__device__ float g_Z[33554432];     // [B][256][TF] permuted attention output
__device__ float g_Yp[33554432];    // [B][256][TF] final conv output (pre-norm)
__device__ float2 g_part[12288];    // partial (sum, sumsq) from GEMM epilogues
__device__ float2 g_stats[32];      // (mu, rstd): [0..23] qkv groups, [24..25] final

// -------- PTX helpers (portable; no "a"-gated features) --------
__device__ __forceinline__ uint32_t smem_u32(const void* p) {
    uint32_t a;
    asm("{ .reg .u64 t; cvta.to.shared.u64 t, %1; cvt.u32.u64 %0, t; }" : "=r"(a) : "l"(p));
    return a;
}
#define CP16(dst, src) \
    asm volatile("cp.async.cg.shared.global [%0], [%1], 16;" :: "r"(dst), "l"(src))
#define CP_COMMIT() asm volatile("cp.async.commit_group;" ::: "memory")
#define CP_WAIT1()  asm volatile("cp.async.wait_group 1;" ::: "memory")
#define CP_WAIT0()  asm volatile("cp.async.wait_group 0;" ::: "memory")

// Raw fp32 bits into tf32 mma: tensor core reads the high 19 bits (truncation).
__device__ __forceinline__ void mma_tf32(float c[4], const uint32_t a[4], const uint32_t b[2]) {
    asm volatile(
        "mma.sync.aligned.m16n8k8.row.col.f32.tf32.tf32.f32 "
        "{%0,%1,%2,%3}, {%4,%5,%6,%7}, {%8,%9}, {%0,%1,%2,%3};"
        : "+f"(c[0]), "+f"(c[1]), "+f"(c[2]), "+f"(c[3])
        : "r"(a[0]), "r"(a[1]), "r"(a[2]), "r"(a[3]), "r"(b[0]), "r"(b[1]));
}
__device__ __forceinline__ float napply(float v, float gg, float of) {
    float y = fmaf(v, gg, of);
    return (y >= 0.f) ? y : 0.25f * y;
}

// ---------------------------------------------------------------------------
// tf32 mma.sync conv GEMM (cp.async double-buffered, raw fp32 operands):
//   Out[tens*2+b][o][j] = bias[o] + sum_c W[o][c] * X[b][c][j]
// Block 128(o) x 128(j), K-chunks of 32; 8 warps, each 4x4 m16n8k8.
// Dynamic smem (words): Ws[2][128*36] @0/4608, Xs[2][32*136] @9216/13568.
// Epilogue fuses bias + per-64-channel-group (sum,sumsq) partials.
// ---------------------------------------------------------------------------
__global__ void __launch_bounds__(256, 2) conv_mma_kernel(
    const float* __restrict__ X, float* __restrict__ Out,
    const float* __restrict__ W0, const float* __restrict__ W1, const float* __restrict__ W2,
    const float* __restrict__ b0_, const float* __restrict__ b1_, const float* __restrict__ b2_,
    float2* __restrict__ part)
{
    extern __shared__ __align__(16) uint32_t dsm[];
    const uint32_t sb = smem_u32(dsm);

    const int bb = blockIdx.z;
    const int y = blockIdx.y;
    const int tens = y >> 1;
    const int o0 = (y & 1) * 128;
    const int j0 = blockIdx.x * 128;
    const float* W    = (tens == 0) ? W0 : (tens == 1) ? W1 : W2;
    const float* bias = (tens == 0) ? b0_ : (tens == 1) ? b1_ : b2_;
    const float* Xb = X + (size_t)bb * (256 * (size_t)TFsz);
    float* O = Out + ((size_t)tens * 2 + bb) * (256 * (size_t)TFsz);

    const int tid = threadIdx.x;
    const int w = tid >> 5, l = tid & 31;
    const int g = l >> 2, t = l & 3;
    const int orow = w >> 2, jcol = w & 3;

    const int wrow0 = tid >> 3, wc4 = tid & 7;   // W copy coords (+it*32 rows)
    const int xr0 = tid >> 5, xc4 = tid & 31;    // X copy coords (+it*8 rows)

    float c[4][4][4];
#pragma unroll
    for (int mt = 0; mt < 4; mt++)
#pragma unroll
        for (int nt = 0; nt < 4; nt++)
#pragma unroll
            for (int i = 0; i < 4; i++) c[mt][nt][i] = 0.f;

#define CONV_ISSUE(KC, BUF) do {                                              \
    uint32_t wdst = sb + (BUF) * 18432;                                       \
    uint32_t xdst = sb + 36864 + (BUF) * 17408;                               \
    _Pragma("unroll")                                                         \
    for (int it = 0; it < 4; it++) {                                          \
        int row = wrow0 + it * 32;                                            \
        CP16(wdst + (row * 36 + wc4 * 4) * 4,                                 \
             &W[(size_t)(o0 + row) * 256 + (KC) * 32 + wc4 * 4]);             \
        int xr = xr0 + it * 8;                                                \
        CP16(xdst + (xr * 136 + xc4 * 4) * 4,                                 \
             &Xb[(size_t)((KC) * 32 + xr) * TFsz + j0 + xc4 * 4]);            \
    }                                                                         \
    CP_COMMIT();                                                              \
} while (0)

    CONV_ISSUE(0, 0);
    for (int kc = 0; kc < 8; kc++) {
        const int buf = kc & 1;
        if (kc < 7) { CONV_ISSUE(kc + 1, buf ^ 1); CP_WAIT1(); }
        else        { CP_WAIT0(); }
        __syncthreads();

        const uint32_t* Wsb = dsm + buf * 4608;
        const uint32_t* Xsb = dsm + 9216 + buf * 4352;
#pragma unroll
        for (int ks = 0; ks < 4; ks++) {
            const int kk = ks * 8;
            uint32_t a[4][4], b[4][2];
#pragma unroll
            for (int mt = 0; mt < 4; mt++) {
                int ow = orow * 64 + mt * 16 + g;
                a[mt][0] = Wsb[ow * 36 + kk + t];
                a[mt][1] = Wsb[(ow + 8) * 36 + kk + t];
                a[mt][2] = Wsb[ow * 36 + kk + t + 4];
                a[mt][3] = Wsb[(ow + 8) * 36 + kk + t + 4];
            }
#pragma unroll
            for (int nt = 0; nt < 4; nt++) {
                int jw = jcol * 32 + nt * 8 + g;
                b[nt][0] = Xsb[(kk + t) * 136 + jw];
                b[nt][1] = Xsb[(kk + t + 4) * 136 + jw];
            }
#pragma unroll
            for (int mt = 0; mt < 4; mt++)
#pragma unroll
                for (int nt = 0; nt < 4; nt++)
                    mma_tf32(c[mt][nt], a[mt], b[nt]);
        }
        __syncthreads();
    }
#undef CONV_ISSUE

    float bl[4], bh[4];
#pragma unroll
    for (int mt = 0; mt < 4; mt++) {
        bl[mt] = __ldg(&bias[o0 + orow * 64 + mt * 16 + g]);
        bh[mt] = __ldg(&bias[o0 + orow * 64 + mt * 16 + g + 8]);
    }
    float s = 0.f, sq = 0.f;
#pragma unroll
    for (int mt = 0; mt < 4; mt++) {
        const int o_lo = o0 + orow * 64 + mt * 16 + g;
#pragma unroll
        for (int nt = 0; nt < 4; nt++) {
            const int jj = j0 + jcol * 32 + nt * 8 + 2 * t;
            float v0 = c[mt][nt][0] + bl[mt];
            float v1 = c[mt][nt][1] + bl[mt];
            float v2 = c[mt][nt][2] + bh[mt];
            float v3 = c[mt][nt][3] + bh[mt];
            *reinterpret_cast<float2*>(&O[(size_t)o_lo * TFsz + jj]) = make_float2(v0, v1);
            *reinterpret_cast<float2*>(&O[(size_t)(o_lo + 8) * TFsz + jj]) = make_float2(v2, v3);
            s  += (v0 + v1) + (v2 + v3);
            sq += (v0 * v0 + v1 * v1) + (v2 * v2 + v3 * v3);
        }
    }

    __syncthreads();
    float* redS = reinterpret_cast<float*>(dsm);
    float* redQ = redS + 256;
    redS[tid] = s; redQ[tid] = sq;
    __syncthreads();
    const int r = tid & 127;
    for (int off = 64; off > 0; off >>= 1) {
        if (r < off) { redS[tid] += redS[tid + off]; redQ[tid] += redQ[tid + off]; }
        __syncthreads();
    }
    if (r == 0) {
        int og = (y & 1) * 2 + (tid >> 7);
        part[(((size_t)tens * 2 + bb) * 4 + og) * 512 + blockIdx.x] =
            make_float2(redS[tid], redQ[tid]);
    }
}

// ---------------------------------------------------------------------------
// Final reduction over `count` consecutive partials per group -> (mu, rstd)
// ---------------------------------------------------------------------------
__global__ void __launch_bounds__(256) reduce_final_kernel(
    const float2* __restrict__ part, float2* __restrict__ stats, int count, float inv_n)
{
    const int g = blockIdx.x;
    float s = 0.f, s2 = 0.f;
    for (int i = threadIdx.x; i < count; i += 256) {
        float2 v = part[(size_t)g * count + i];
        s += v.x; s2 += v.y;
    }
    __shared__ float sh[256], sh2[256];
    int t = threadIdx.x;
    sh[t] = s; sh2[t] = s2;
    __syncthreads();
    for (int off = 128; off > 0; off >>= 1) {
        if (t < off) { sh[t] += sh[t + off]; sh2[t] += sh2[t + off]; }
        __syncthreads();
    }
    if (t == 0) {
        float mu = sh[0] * inv_n;
        float var = fmaxf(sh2[0] * inv_n - mu * mu, 0.f);
        stats[g] = make_float2(mu, rsqrtf(var + 1e-6f));
    }
}

// ---------------------------------------------------------------------------
// QK via tf32 mma.sync (NT, split-K x4): Sp[c][g][t][s] = scale*sum Q'(t,k)K'(s,k)
// Norm+PReLU at smem store (raw float bits; mma truncates to tf32).
// grid (4 s-tiles, 4 t-tiles, 32 = g*4+c), 256 threads.
// ---------------------------------------------------------------------------
__global__ void __launch_bounds__(256, 2) qk_mma_kernel(
    const float* __restrict__ gq, const float* __restrict__ betaq,
    const float* __restrict__ gk, const float* __restrict__ betak)
{
    __shared__ __align__(16) float Qs[128][36];
    __shared__ __align__(16) float Ks[128][36];
    __shared__ float sgg[2][64], sof[2][64];

    const int z = blockIdx.z;
    const int g = z >> 2, c = z & 3;
    const int n = g & 3;
    const float* Q  = g_Y3 + (size_t)g * 4194304;
    const float* Km = g_Y3 + 8ull * 4194304 + (size_t)g * 4194304;
    const int t0 = blockIdx.y * 128, s0 = blockIdx.x * 128;
    const int tid = threadIdx.x;
    const int w = tid >> 5, l = tid & 31;
    const int fg = l >> 2, ft = l & 3;
    const int orow = w >> 2, jcol = w & 3;

    if (tid < 128) {
        int which = tid >> 6, h = tid & 63, o = n * 64 + h;
        float2 st = g_stats[which * 8 + g];
        const float* gw = which ? gk : gq;
        const float* bw = which ? betak : betaq;
        float gg = gw[o] * st.y;
        sgg[which][h] = gg;
        sof[which][h] = bw[o] - st.x * gg;
    }
    __syncthreads();

    float acc[4][4][4];
#pragma unroll
    for (int mt = 0; mt < 4; mt++)
#pragma unroll
        for (int nt = 0; nt < 4; nt++)
#pragma unroll
            for (int i = 0; i < 4; i++) acc[mt][nt][i] = 0.f;

    for (int kc = 0; kc < 64; kc++) {
        const int k0 = c * 2048 + kc * 32;
        const int h = k0 >> 7;
        const size_t hb = (size_t)h * 65536 + (size_t)(k0 & 127);
        const float ggq = sgg[0][h], ofq = sof[0][h];
        const float ggk = sgg[1][h], ofk = sof[1][h];
        float4 qv[4], kv[4];
#pragma unroll
        for (int it = 0; it < 4; it++) {
            int i4 = tid + it * 256;
            int r = i4 >> 3, c4 = i4 & 7;
            qv[it] = *reinterpret_cast<const float4*>(&Q[hb + (size_t)(t0 + r) * 128 + c4 * 4]);
            kv[it] = *reinterpret_cast<const float4*>(&Km[hb + (size_t)(s0 + r) * 128 + c4 * 4]);
        }
        __syncthreads();
#pragma unroll
        for (int it = 0; it < 4; it++) {
            int i4 = tid + it * 256;
            int r = i4 >> 3, c4 = i4 & 7;
            float4 uq, uk;
            uq.x = napply(qv[it].x, ggq, ofq);
            uq.y = napply(qv[it].y, ggq, ofq);
            uq.z = napply(qv[it].z, ggq, ofq);
            uq.w = napply(qv[it].w, ggq, ofq);
            *reinterpret_cast<float4*>(&Qs[r][c4 * 4]) = uq;
            uk.x = napply(kv[it].x, ggk, ofk);
            uk.y = napply(kv[it].y, ggk, ofk);
            uk.z = napply(kv[it].z, ggk, ofk);
            uk.w = napply(kv[it].w, ggk, ofk);
            *reinterpret_cast<float4*>(&Ks[r][c4 * 4]) = uk;
        }
        __syncthreads();

#pragma unroll
        for (int ks = 0; ks < 4; ks++) {
            const int kk = ks * 8;
            uint32_t a[4][4], b[4][2];
#pragma unroll
            for (int mt = 0; mt < 4; mt++) {
                int tw = orow * 64 + mt * 16 + fg;
                a[mt][0] = __float_as_uint(Qs[tw][kk + ft]);
                a[mt][1] = __float_as_uint(Qs[tw + 8][kk + ft]);
                a[mt][2] = __float_as_uint(Qs[tw][kk + ft + 4]);
                a[mt][3] = __float_as_uint(Qs[tw + 8][kk + ft + 4]);
            }
#pragma unroll
            for (int nt = 0; nt < 4; nt++) {
                int sw = jcol * 32 + nt * 8 + fg;
                b[nt][0] = __float_as_uint(Ks[sw][kk + ft]);
                b[nt][1] = __float_as_uint(Ks[sw][kk + ft + 4]);
            }
#pragma unroll
            for (int mt = 0; mt < 4; mt++)
#pragma unroll
                for (int nt = 0; nt < 4; nt++)
                    mma_tf32(acc[mt][nt], a[mt], b[nt]);
        }
        __syncthreads();
    }

    const float scale = 0.011048543456039806f;   // 1/sqrt(8192)
    float* Sg = g_Sp + (size_t)c * 2097152 + (size_t)g * 262144;
#pragma unroll
    for (int mt = 0; mt < 4; mt++) {
        const int tl = t0 + orow * 64 + mt * 16 + fg;
#pragma unroll
        for (int nt = 0; nt < 4; nt++) {
            const int sl = s0 + jcol * 32 + nt * 8 + 2 * ft;
            *reinterpret_cast<float2*>(&Sg[(size_t)tl * 512 + sl]) =
                make_float2(acc[mt][nt][0] * scale, acc[mt][nt][1] * scale);
            *reinterpret_cast<float2*>(&Sg[(size_t)(tl + 8) * 512 + sl]) =
                make_float2(acc[mt][nt][2] * scale, acc[mt][nt][3] * scale);
        }
    }
}

// ---------------------------------------------------------------------------
// Row softmax over 512, fusing the split-K partial sum. 4096 blocks.
// ---------------------------------------------------------------------------
__global__ void __launch_bounds__(256) softmax_kernel()
{
    const size_t row = (size_t)blockIdx.x * 512;
    const int t = threadIdx.x;
    float a = 0.f, b = 0.f;
#pragma unroll
    for (int c = 0; c < 4; c++) {
        const float* p = g_Sp + (size_t)c * 2097152 + row;
        a += p[t]; b += p[t + 256];
    }
    __shared__ float sh[256];
    sh[t] = fmaxf(a, b);
    __syncthreads();
    for (int off = 128; off > 0; off >>= 1) {
        if (t < off) sh[t] = fmaxf(sh[t], sh[t + off]);
        __syncthreads();
    }
    float m = sh[0];
    __syncthreads();
    float e0 = __expf(a - m), e1 = __expf(b - m);
    sh[t] = e0 + e1;
    __syncthreads();
    for (int off = 128; off > 0; off >>= 1) {
        if (t < off) sh[t] += sh[t + off];
        __syncthreads();
    }
    float inv = 1.0f / sh[0];
    float* q = g_S + row;
    q[t] = e0 * inv;
    q[t + 256] = e1 * inv;
}

// ---------------------------------------------------------------------------
// PV via tf32 mma.sync, output-transposed: M=f(128), N=t(128), K=s(512).
// Zt[f][t] = sum_s V'[s][f] * P[t][s]  ->  Z[b][n*64+cn][f*512+t]
// Norm+PReLU at smem store (raw bits). grid (64 cn, 4 t-tiles, 8 groups).
// ---------------------------------------------------------------------------
__global__ void __launch_bounds__(256, 2) pv_mma_kernel(
    const float* __restrict__ gv, const float* __restrict__ betav)
{
    __shared__ __align__(16) float Vs[32][136];   // [s][f]
    __shared__ __align__(16) float Ps[128][36];   // [t][s]

    const int g = blockIdx.z;
    const int n = g & 3, bb = g >> 2;
    const float* P = g_S + (size_t)g * 262144;
    const int cn = blockIdx.x;
    const float* Vb = g_Y3 + 16ull * 4194304 + (size_t)g * 4194304 + (size_t)cn * 65536;
    const int t0 = blockIdx.y * 128;
    float* Zb = g_Z + ((size_t)bb * 256 + (size_t)(n * 64 + cn)) * 65536;

    const int tid = threadIdx.x;
    const int w = tid >> 5, l = tid & 31;
    const int fg = l >> 2, ft = l & 3;
    const int orow = w >> 2, jcol = w & 3;

    float2 stv = g_stats[16 + g];
    const float ggv = gv[n * 64 + cn] * stv.y;
    const float ofv = betav[n * 64 + cn] - stv.x * ggv;

    float acc[4][4][4];
#pragma unroll
    for (int mt = 0; mt < 4; mt++)
#pragma unroll
        for (int nt = 0; nt < 4; nt++)
#pragma unroll
            for (int i = 0; i < 4; i++) acc[mt][nt][i] = 0.f;

    for (int kc = 0; kc < 16; kc++) {
        float4 vv[4], pp[4];
#pragma unroll
        for (int it = 0; it < 4; it++) {
            int i4 = tid + it * 256;
            int vr = i4 >> 5, vc4 = i4 & 31;
            vv[it] = *reinterpret_cast<const float4*>(&Vb[(size_t)(kc * 32 + vr) * 128 + vc4 * 4]);
            int pr = i4 >> 3, pc4 = i4 & 7;
            pp[it] = *reinterpret_cast<const float4*>(&P[(size_t)(t0 + pr) * 512 + kc * 32 + pc4 * 4]);
        }
        __syncthreads();
#pragma unroll
        for (int it = 0; it < 4; it++) {
            int i4 = tid + it * 256;
            int vr = i4 >> 5, vc4 = i4 & 31;
            float4 u;
            u.x = napply(vv[it].x, ggv, ofv);
            u.y = napply(vv[it].y, ggv, ofv);
            u.z = napply(vv[it].z, ggv, ofv);
            u.w = napply(vv[it].w, ggv, ofv);
            *reinterpret_cast<float4*>(&Vs[vr][vc4 * 4]) = u;
            int pr = i4 >> 3, pc4 = i4 & 7;
            *reinterpret_cast<float4*>(&Ps[pr][pc4 * 4]) = pp[it];
        }
        __syncthreads();

#pragma unroll
        for (int ks = 0; ks < 4; ks++) {
            const int kk = ks * 8;
            uint32_t a[4][4], b[4][2];
#pragma unroll
            for (int mt = 0; mt < 4; mt++) {
                int fw = orow * 64 + mt * 16 + fg;
                a[mt][0] = __float_as_uint(Vs[kk + ft][fw]);
                a[mt][1] = __float_as_uint(Vs[kk + ft][fw + 8]);
                a[mt][2] = __float_as_uint(Vs[kk + ft + 4][fw]);
                a[mt][3] = __float_as_uint(Vs[kk + ft + 4][fw + 8]);
            }
#pragma unroll
            for (int nt = 0; nt < 4; nt++) {
                int tw = jcol * 32 + nt * 8 + fg;
                b[nt][0] = __float_as_uint(Ps[tw][kk + ft]);
                b[nt][1] = __float_as_uint(Ps[tw][kk + ft + 4]);
            }
#pragma unroll
            for (int mt = 0; mt < 4; mt++)
#pragma unroll
                for (int nt = 0; nt < 4; nt++)
                    mma_tf32(acc[mt][nt], a[mt], b[nt]);
        }
        __syncthreads();
    }

    // C: (m=f, n=t_local); c0/c1 consecutive t, c2/c3 at f+8
#pragma unroll
    for (int mt = 0; mt < 4; mt++) {
        const int f = orow * 64 + mt * 16 + fg;
#pragma unroll
        for (int nt = 0; nt < 4; nt++) {
            const int tt = t0 + jcol * 32 + nt * 8 + 2 * ft;
            *reinterpret_cast<float2*>(&Zb[(size_t)f * 512 + tt]) =
                make_float2(acc[mt][nt][0], acc[mt][nt][1]);
            *reinterpret_cast<float2*>(&Zb[(size_t)(f + 8) * 512 + tt]) =
                make_float2(acc[mt][nt][2], acc[mt][nt][3]);
        }
    }
}

// ---------------------------------------------------------------------------
// Final: out = PReLU(norm(Yp)*gp + betap) + x
// ---------------------------------------------------------------------------
__global__ void __launch_bounds__(256) apply_final_kernel(
    const float* __restrict__ x, const float* __restrict__ gp,
    const float* __restrict__ betap, const float2* __restrict__ stats2,
    float* __restrict__ out)
{
    size_t i = ((size_t)blockIdx.x * 256 + threadIdx.x) * 4;
    int r = (int)(i >> 16);
    int bidx = r >> 8;
    int o = r & 255;
    float2 st = stats2[bidx];
    float gg = gp[o] * st.y;
    float ofs = betap[o] - st.x * gg;
    float4 v  = *reinterpret_cast<const float4*>(&g_Yp[i]);
    float4 xr = *reinterpret_cast<const float4*>(&x[i]);
    v.x = fmaf(v.x, gg, ofs); v.x = ((v.x >= 0.f) ? v.x : 0.25f * v.x) + xr.x;
    v.y = fmaf(v.y, gg, ofs); v.y = ((v.y >= 0.f) ? v.y : 0.25f * v.y) + xr.y;
    v.z = fmaf(v.z, gg, ofs); v.z = ((v.z >= 0.f) ? v.z : 0.25f * v.z) + xr.z;
    v.w = fmaf(v.w, gg, ofs); v.w = ((v.w >= 0.f) ? v.w : 0.25f * v.w) + xr.w;
    *reinterpret_cast<float4*>(&out[i]) = v;
}

// ---------------------------------------------------------------------------
extern "C" void kernel_launch(void* const* d_in, const int* in_sizes, int n_in,
                              void* d_out, int out_size)
{
    const float* x     = (const float*)d_in[0];
    const float* Wq    = (const float*)d_in[1];
    const float* bq    = (const float*)d_in[2];
    const float* gq    = (const float*)d_in[3];
    const float* betaq = (const float*)d_in[4];
    const float* Wk    = (const float*)d_in[5];
    const float* bk    = (const float*)d_in[6];
    const float* gk    = (const float*)d_in[7];
    const float* betak = (const float*)d_in[8];
    const float* Wv    = (const float*)d_in[9];
    const float* bv    = (const float*)d_in[10];
    const float* gv    = (const float*)d_in[11];
    const float* betav = (const float*)d_in[12];
    const float* Wp    = (const float*)d_in[13];
    const float* bp    = (const float*)d_in[14];
    const float* gp    = (const float*)d_in[15];
    const float* betap = (const float*)d_in[16];

    float *Y3, *Z, *Yp;
    float2 *part, *stats;
    cudaGetSymbolAddress((void**)&Y3,   g_Y3);
    cudaGetSymbolAddress((void**)&Z,    g_Z);
    cudaGetSymbolAddress((void**)&Yp,   g_Yp);
    cudaGetSymbolAddress((void**)&part, g_part);
    cudaGetSymbolAddress((void**)&stats, g_stats);

    const int SM_CONV = 71680;   // 2*(128*36 + 32*136) words * 4B
    cudaFuncSetAttribute(conv_mma_kernel, cudaFuncAttributeMaxDynamicSharedMemorySize, SM_CONV);

    // 1) QKV projections via tf32 mma.sync (cp.async, + fused norm partials)
    conv_mma_kernel<<<dim3(512, 6, 2), 256, SM_CONV>>>(x, Y3, Wq, Wk, Wv, bq, bk, bv, part);
    // 2) finalize QKV GroupNorm stats: 24 groups x 512 partials
    reduce_final_kernel<<<24, 256>>>(part, stats, 512, 1.0f / 4194304.0f);
    // 3) S partials = scale * Q'K'^T  (mma.sync, split-K x4, norm fused)
    qk_mma_kernel<<<dim3(4, 4, 32), 256>>>(gq, betaq, gk, betak);
    // 4) softmax rows (fuses split-K reduction)
    softmax_kernel<<<4096, 256>>>();
    // 5) Vo = P V' (mma.sync, norm fused), permuted write into Z
    pv_mma_kernel<<<dim3(64, 4, 8), 256>>>(gv, betav);
    // 6) final projection via tf32 mma.sync (cp.async, + fused norm partials)
    conv_mma_kernel<<<dim3(512, 2, 2), 256, SM_CONV>>>(Z, Yp, Wp, Wp, Wp, bp, bp, bp, part);
    // 7) finalize per-sample stats: 2 groups x 2048 partials
    reduce_final_kernel<<<2, 256>>>(part, stats + 24, 2048, 1.0f / 16777216.0f);
    // 8) normalize + PReLU + residual
    apply_final_kernel<<<32768, 256>>>(x, gp, betap, stats + 24, (float*)d_out);
}